// round 2
// baseline (speedup 1.0000x reference)
#include <cuda_runtime.h>
#include <math.h>

// Problem constants
#define BATCH 2
#define SEQ   1024
#define TOK   (BATCH*SEQ)      // 2048
#define DMODEL 1024
#define NHEAD 16
#define DK    64
#define FF    4096
#define NLAYER 4
#define LNEPS 1e-5f

#define H_ELEMS ((size_t)TOK * DMODEL)                    // 2,097,152
#define AW_PER_LAYER ((size_t)BATCH * NHEAD * SEQ * SEQ)  // 33,554,432

// ------------------------- scratch (static device globals) -------------------------
__device__ float g_h  [TOK * DMODEL];
__device__ float g_q  [TOK * DMODEL];
__device__ float g_k  [TOK * DMODEL];
__device__ float g_v  [TOK * DMODEL];
__device__ float g_ctx[TOK * DMODEL];
__device__ float g_res[TOK * DMODEL];
__device__ float g_ff [TOK * FF];

// ------------------------- embedding + positional encoding -------------------------
__global__ void embed_kernel(const int* __restrict__ ids, const float* __restrict__ emb,
                             float* __restrict__ h) {
    int token = blockIdx.x;                       // 0..2047
    int d = blockIdx.y * 256 + threadIdx.x;       // 0..1023
    int s = token & (SEQ - 1);
    int id = ids[token];
    float c_even = (float)((d >> 1) << 1);
    float div = __expf(c_even * (-logf(10000.0f) / (float)DMODEL));
    float ang = (float)s * div;
    float pe = (d & 1) ? cosf(ang) : sinf(ang);
    h[(size_t)token * DMODEL + d] = emb[(size_t)id * DMODEL + d] * 32.0f + pe;
}

// ------------------------- generic SGEMM: C[M,N] = A[M,K] @ B[K,N] + bias -----------
// 128x128 tile, BK=8, 256 threads, 8x8 per-thread microtile. M,N%128==0, K%8==0.
template <int RELU>
__global__ void sgemm128(const float* __restrict__ A, const float* __restrict__ B,
                         const float* __restrict__ bias, float* __restrict__ C,
                         int M, int N, int K) {
    __shared__ float As[8][128];
    __shared__ float Bs[8][128];
    const int tid = threadIdx.x;
    const int brow = blockIdx.y * 128;
    const int bcol = blockIdx.x * 128;

    const int arow = tid >> 1;            // 0..127
    const int acol = (tid & 1) * 4;       // 0 or 4
    const int brl  = tid >> 5;            // 0..7
    const int bcl  = (tid & 31) * 4;      // 0..124

    const int ty = tid >> 4, tx = tid & 15;

    float acc[8][8];
    #pragma unroll
    for (int i = 0; i < 8; i++)
        #pragma unroll
        for (int j = 0; j < 8; j++) acc[i][j] = 0.0f;

    for (int k0 = 0; k0 < K; k0 += 8) {
        float4 a = *(const float4*)(A + (size_t)(brow + arow) * K + k0 + acol);
        As[acol + 0][arow] = a.x;
        As[acol + 1][arow] = a.y;
        As[acol + 2][arow] = a.z;
        As[acol + 3][arow] = a.w;
        float4 b = *(const float4*)(B + (size_t)(k0 + brl) * N + bcol + bcl);
        *(float4*)&Bs[brl][bcl] = b;
        __syncthreads();
        #pragma unroll
        for (int kk = 0; kk < 8; kk++) {
            float ar[8], br[8];
            #pragma unroll
            for (int i = 0; i < 8; i++) ar[i] = As[kk][ty * 8 + i];
            #pragma unroll
            for (int j = 0; j < 8; j++) br[j] = Bs[kk][tx * 8 + j];
            #pragma unroll
            for (int i = 0; i < 8; i++)
                #pragma unroll
                for (int j = 0; j < 8; j++) acc[i][j] += ar[i] * br[j];
        }
        __syncthreads();
    }

    #pragma unroll
    for (int i = 0; i < 8; i++) {
        int row = brow + ty * 8 + i;
        #pragma unroll
        for (int j = 0; j < 8; j += 4) {
            int col = bcol + tx * 8 + j;
            float4 o;
            o.x = acc[i][j + 0] + bias[col + 0];
            o.y = acc[i][j + 1] + bias[col + 1];
            o.z = acc[i][j + 2] + bias[col + 2];
            o.w = acc[i][j + 3] + bias[col + 3];
            if (RELU) {
                o.x = fmaxf(o.x, 0.0f); o.y = fmaxf(o.y, 0.0f);
                o.z = fmaxf(o.z, 0.0f); o.w = fmaxf(o.w, 0.0f);
            }
            *(float4*)(C + (size_t)row * N + col) = o;
        }
    }
}

// ------------------------- attention scores: aw = scale * Q @ K^T -------------------
// per (b,h): [1024,64] x [1024,64]^T -> [1024,1024]. 64x64 output tile per block.
__global__ void attn_scores_kernel(const float* __restrict__ q, const float* __restrict__ k,
                                   float* __restrict__ aw) {
    const int bh = blockIdx.z;                 // 0..31
    const int b = bh >> 4, hh = bh & 15;
    const float* qb = q + (size_t)b * SEQ * DMODEL + hh * DK;
    const float* kb = k + (size_t)b * SEQ * DMODEL + hh * DK;
    const int qt = blockIdx.y * 64, kt = blockIdx.x * 64;

    __shared__ float Qs[64][65];
    __shared__ float Ks[64][65];
    const int tid = threadIdx.x;
    for (int i = tid; i < 64 * 64; i += 256) {
        int r = i >> 6, c = i & 63;
        Qs[r][c] = qb[(size_t)(qt + r) * DMODEL + c];
        Ks[r][c] = kb[(size_t)(kt + r) * DMODEL + c];
    }
    __syncthreads();

    const int ty = tid >> 4, tx = tid & 15;
    float acc[4][4];
    #pragma unroll
    for (int i = 0; i < 4; i++)
        #pragma unroll
        for (int j = 0; j < 4; j++) acc[i][j] = 0.0f;

    for (int kk = 0; kk < 64; kk++) {
        float qr[4], kr[4];
        #pragma unroll
        for (int i = 0; i < 4; i++) qr[i] = Qs[ty * 4 + i][kk];
        #pragma unroll
        for (int j = 0; j < 4; j++) kr[j] = Ks[tx * 4 + j][kk];
        #pragma unroll
        for (int i = 0; i < 4; i++)
            #pragma unroll
            for (int j = 0; j < 4; j++) acc[i][j] += qr[i] * kr[j];
    }

    const float scale = 0.125f;  // 1/sqrt(64)
    float* out = aw + (size_t)bh * SEQ * SEQ;
    #pragma unroll
    for (int i = 0; i < 4; i++) {
        int row = qt + ty * 4 + i;
        #pragma unroll
        for (int j = 0; j < 4; j++) {
            out[(size_t)row * SEQ + kt + tx * 4 + j] = acc[i][j] * scale;
        }
    }
}

// ------------------------- row softmax over 1024 elements ---------------------------
__global__ void softmax1024(float* __restrict__ p0) {
    float* p = p0 + (size_t)blockIdx.x * 1024;
    const int tid = threadIdx.x;
    __shared__ float red[256];

    float v[4];
    float m = -INFINITY;
    #pragma unroll
    for (int i = 0; i < 4; i++) {
        v[i] = p[tid + i * 256];
        m = fmaxf(m, v[i]);
    }
    red[tid] = m;
    __syncthreads();
    for (int s = 128; s > 0; s >>= 1) {
        if (tid < s) red[tid] = fmaxf(red[tid], red[tid + s]);
        __syncthreads();
    }
    m = red[0];
    __syncthreads();

    float sum = 0.0f;
    #pragma unroll
    for (int i = 0; i < 4; i++) {
        v[i] = expf(v[i] - m);
        sum += v[i];
    }
    red[tid] = sum;
    __syncthreads();
    for (int s = 128; s > 0; s >>= 1) {
        if (tid < s) red[tid] += red[tid + s];
        __syncthreads();
    }
    float inv = 1.0f / red[0];
    #pragma unroll
    for (int i = 0; i < 4; i++) p[tid + i * 256] = v[i] * inv;
}

// ------------------------- ctx = aw @ V  -> [B*S, D] layout -------------------------
// per (b,h): [1024,1024] x [1024,64] -> [1024,64]. 64-row tile per block.
__global__ void attn_ctx_kernel(const float* __restrict__ aw, const float* __restrict__ v,
                                float* __restrict__ ctx) {
    const int bh = blockIdx.y;                // 0..31
    const int b = bh >> 4, hh = bh & 15;
    const int rt = blockIdx.x * 64;           // row tile
    const float* awb = aw + (size_t)bh * SEQ * SEQ;
    const float* vb = v + (size_t)b * SEQ * DMODEL + hh * DK;

    __shared__ float Aws[64][65];
    __shared__ float Vs[64][65];
    const int tid = threadIdx.x;
    const int ty = tid >> 4, tx = tid & 15;

    float acc[4][4];
    #pragma unroll
    for (int i = 0; i < 4; i++)
        #pragma unroll
        for (int j = 0; j < 4; j++) acc[i][j] = 0.0f;

    for (int k0 = 0; k0 < SEQ; k0 += 64) {
        for (int i = tid; i < 64 * 64; i += 256) {
            int r = i >> 6, c = i & 63;
            Aws[r][c] = awb[(size_t)(rt + r) * SEQ + k0 + c];
            Vs[r][c]  = vb[(size_t)(k0 + r) * DMODEL + c];
        }
        __syncthreads();
        #pragma unroll
        for (int kk = 0; kk < 64; kk++) {
            float ar[4], br[4];
            #pragma unroll
            for (int i = 0; i < 4; i++) ar[i] = Aws[ty * 4 + i][kk];
            #pragma unroll
            for (int j = 0; j < 4; j++) br[j] = Vs[kk][tx * 4 + j];
            #pragma unroll
            for (int i = 0; i < 4; i++)
                #pragma unroll
                for (int j = 0; j < 4; j++) acc[i][j] += ar[i] * br[j];
        }
        __syncthreads();
    }

    #pragma unroll
    for (int i = 0; i < 4; i++) {
        int row = b * SEQ + rt + ty * 4 + i;
        #pragma unroll
        for (int j = 0; j < 4; j++) {
            ctx[(size_t)row * DMODEL + hh * DK + tx * 4 + j] = acc[i][j];
        }
    }
}

// ------------------------- fused residual-add + LayerNorm ---------------------------
__global__ void add_ln_kernel(const float* __restrict__ x, const float* __restrict__ r,
                              const float* __restrict__ g, const float* __restrict__ b,
                              float* __restrict__ out) {
    const size_t row = blockIdx.x;
    const int tid = threadIdx.x;
    __shared__ float red[256];
    __shared__ float s_mu, s_rinv;

    float v[4];
    float s = 0.0f;
    #pragma unroll
    for (int i = 0; i < 4; i++) {
        int c = tid + i * 256;
        v[i] = x[row * DMODEL + c] + r[row * DMODEL + c];
        s += v[i];
    }
    red[tid] = s;
    __syncthreads();
    for (int t = 128; t > 0; t >>= 1) {
        if (tid < t) red[tid] += red[tid + t];
        __syncthreads();
    }
    if (tid == 0) s_mu = red[0] * (1.0f / DMODEL);
    __syncthreads();
    float mu = s_mu;

    float sq = 0.0f;
    #pragma unroll
    for (int i = 0; i < 4; i++) {
        float d = v[i] - mu;
        sq += d * d;
    }
    red[tid] = sq;
    __syncthreads();
    for (int t = 128; t > 0; t >>= 1) {
        if (tid < t) red[tid] += red[tid + t];
        __syncthreads();
    }
    if (tid == 0) s_rinv = rsqrtf(red[0] * (1.0f / DMODEL) + LNEPS);
    __syncthreads();
    float rinv = s_rinv;

    #pragma unroll
    for (int i = 0; i < 4; i++) {
        int c = tid + i * 256;
        out[row * DMODEL + c] = (v[i] - mu) * rinv * g[c] + b[c];
    }
}

// ------------------------- final copy h -> d_out ------------------------------------
__global__ void copy_kernel(const float* __restrict__ src, float* __restrict__ dst, size_t n) {
    size_t i = (size_t)blockIdx.x * blockDim.x + threadIdx.x;
    if (i < n) dst[i] = src[i];
}

// ====================================================================================
extern "C" void kernel_launch(void* const* d_in, const int* in_sizes, int n_in,
                              void* d_out, int out_size) {
    const int*   ids  = (const int*)  d_in[0];
    const float* emb  = (const float*)d_in[1];
    const float* Wq   = (const float*)d_in[2];
    const float* bq   = (const float*)d_in[3];
    const float* Wk   = (const float*)d_in[4];
    const float* bk   = (const float*)d_in[5];
    const float* Wv   = (const float*)d_in[6];
    const float* bv   = (const float*)d_in[7];
    const float* Wo   = (const float*)d_in[8];
    const float* bo   = (const float*)d_in[9];
    const float* W1   = (const float*)d_in[10];
    const float* b1   = (const float*)d_in[11];
    const float* W2   = (const float*)d_in[12];
    const float* b2   = (const float*)d_in[13];
    const float* ln1g = (const float*)d_in[14];
    const float* ln1b = (const float*)d_in[15];
    const float* ln2g = (const float*)d_in[16];
    const float* ln2b = (const float*)d_in[17];

    float* out = (float*)d_out;

    float *h, *q, *k, *v, *ctx, *res, *ff;
    cudaGetSymbolAddress((void**)&h,   g_h);
    cudaGetSymbolAddress((void**)&q,   g_q);
    cudaGetSymbolAddress((void**)&k,   g_k);
    cudaGetSymbolAddress((void**)&v,   g_v);
    cudaGetSymbolAddress((void**)&ctx, g_ctx);
    cudaGetSymbolAddress((void**)&res, g_res);
    cudaGetSymbolAddress((void**)&ff,  g_ff);

    // 1. embedding + PE
    embed_kernel<<<dim3(TOK, DMODEL / 256), 256>>>(ids, emb, h);

    dim3 gemmDD(DMODEL / 128, TOK / 128);   // (8,16)  N=1024
    dim3 gemmDF(FF / 128, TOK / 128);       // (32,16) N=4096

    for (int l = 0; l < NLAYER; l++) {
        const float* Wq_l = Wq + (size_t)l * DMODEL * DMODEL;
        const float* Wk_l = Wk + (size_t)l * DMODEL * DMODEL;
        const float* Wv_l = Wv + (size_t)l * DMODEL * DMODEL;
        const float* Wo_l = Wo + (size_t)l * DMODEL * DMODEL;
        const float* W1_l = W1 + (size_t)l * DMODEL * FF;
        const float* W2_l = W2 + (size_t)l * FF * DMODEL;
        const float* bq_l = bq + (size_t)l * DMODEL;
        const float* bk_l = bk + (size_t)l * DMODEL;
        const float* bv_l = bv + (size_t)l * DMODEL;
        const float* bo_l = bo + (size_t)l * DMODEL;
        const float* b1_l = b1 + (size_t)l * FF;
        const float* b2_l = b2 + (size_t)l * DMODEL;

        float* aw = out + H_ELEMS + (size_t)l * AW_PER_LAYER;

        // QKV projections
        sgemm128<0><<<gemmDD, 256>>>(h, Wq_l, bq_l, q, TOK, DMODEL, DMODEL);
        sgemm128<0><<<gemmDD, 256>>>(h, Wk_l, bk_l, k, TOK, DMODEL, DMODEL);
        sgemm128<0><<<gemmDD, 256>>>(h, Wv_l, bv_l, v, TOK, DMODEL, DMODEL);

        // scores + softmax (written directly into d_out attn region)
        attn_scores_kernel<<<dim3(SEQ / 64, SEQ / 64, BATCH * NHEAD), 256>>>(q, k, aw);
        softmax1024<<<BATCH * NHEAD * SEQ, 256>>>(aw);

        // ctx = aw @ V
        attn_ctx_kernel<<<dim3(SEQ / 64, BATCH * NHEAD), 256>>>(aw, v, ctx);

        // output projection + residual LN
        sgemm128<0><<<gemmDD, 256>>>(ctx, Wo_l, bo_l, res, TOK, DMODEL, DMODEL);
        add_ln_kernel<<<TOK, 256>>>(h, res, ln1g + (size_t)l * DMODEL,
                                    ln1b + (size_t)l * DMODEL, h);

        // FFN
        sgemm128<1><<<gemmDF, 256>>>(h, W1_l, b1_l, ff, TOK, FF, DMODEL);
        sgemm128<0><<<gemmDD, 256>>>(ff, W2_l, b2_l, res, TOK, DMODEL, FF);
        add_ln_kernel<<<TOK, 256>>>(h, res, ln2g + (size_t)l * DMODEL,
                                    ln2b + (size_t)l * DMODEL, h);
    }

    // final hidden states -> start of d_out
    copy_kernel<<<(unsigned)((H_ELEMS + 255) / 256), 256>>>(h, out, H_ELEMS);
}

// round 4
// speedup vs baseline: 3.3838x; 3.3838x over previous
#include <cuda_runtime.h>
#include <cstdint>
#include <math.h>

// Problem constants
#define BATCH 2
#define SEQ   1024
#define TOK   (BATCH*SEQ)      // 2048
#define DMODEL 1024
#define NHEAD 16
#define DK    64
#define FF    4096
#define NLAYER 4
#define LNEPS 1e-5f

#define H_ELEMS ((size_t)TOK * DMODEL)
#define AW_PER_LAYER ((size_t)BATCH * NHEAD * SEQ * SEQ)

// ------------------------- scratch (static device globals) -------------------------
__device__ float g_h  [TOK * DMODEL];
__device__ float g_q  [TOK * DMODEL];
__device__ float g_k  [TOK * DMODEL];
__device__ float g_v  [TOK * DMODEL];
__device__ float g_ctx[TOK * DMODEL];
__device__ float g_res[TOK * DMODEL];
__device__ float g_ff [TOK * FF];

// ------------------------------ tf32 helpers ---------------------------------------
__device__ __forceinline__ float f2tf32f(float x) {
    uint32_t r;
    asm("cvt.rna.tf32.f32 %0, %1;" : "=r"(r) : "f"(x));
    return __uint_as_float(r);
}

__device__ __forceinline__ void mma1688(float c[4], const float a[4], const float b[2]) {
    asm volatile(
        "mma.sync.aligned.m16n8k8.row.col.f32.tf32.tf32.f32 "
        "{%0,%1,%2,%3}, {%4,%5,%6,%7}, {%8,%9}, {%0,%1,%2,%3};"
        : "+f"(c[0]), "+f"(c[1]), "+f"(c[2]), "+f"(c[3])
        : "r"(__float_as_uint(a[0])), "r"(__float_as_uint(a[1])),
          "r"(__float_as_uint(a[2])), "r"(__float_as_uint(a[3])),
          "r"(__float_as_uint(b[0])), "r"(__float_as_uint(b[1])));
}

// ===================== templated tf32 mma.sync GEMM core ============================
// C[M,N] = scale * A[M,K] @ B[K,N] (+bias) (ReLU optional)
// TRANSB=1: B provided as [N,K] row-major (used for Q@K^T).
// 256 threads, BK=32, warp tile WM x WN of m16n8k8 fragments.
template <int BM, int BN, int BK, int WM, int WN, int TRANSB, int RELU, int HASBIAS>
__device__ __forceinline__ void gemm_core(
    const float* __restrict__ A, int lda,
    const float* __restrict__ B, int ldb,
    const float* __restrict__ bias,
    float* __restrict__ C, int ldc,
    int K, float scale)
{
    static_assert(BK == 32, "BK must be 32");
    constexpr int BKP = BK + 4;
    constexpr int BNP = BN + 8;
    __shared__ float As[BM][BKP];
    __shared__ float Bs[BK][BNP];

    const int tid = threadIdx.x;
    const int m0 = blockIdx.y * BM;
    const int n0 = blockIdx.x * BN;
    A += (size_t)m0 * lda;
    if (TRANSB) B += (size_t)n0 * ldb;
    else        B += n0;
    C += (size_t)m0 * ldc + n0;
    if (HASBIAS) bias += n0;

    constexpr int LA = BM * BK / (4 * 256);
    constexpr int LB = BK * BN / (4 * 256);
    float4 pa[LA], pb[LB];

    const int NC = K / BK;

    // ---- global prefetch loaders (float4) ----
    auto loadA = [&](int c) {
        #pragma unroll
        for (int t = 0; t < LA; t++) {
            int i = tid + t * 256;
            int r = i >> 3;              // BK/4 == 8 groups per row
            int cc = (i & 7) * 4;
            pa[t] = *(const float4*)(A + (size_t)r * lda + c * BK + cc);
        }
    };
    auto loadB = [&](int c) {
        if (TRANSB) {
            #pragma unroll
            for (int t = 0; t < LB; t++) {
                int i = tid + t * 256;
                int n = i >> 3;
                int kg = (i & 7) * 4;
                pb[t] = *(const float4*)(B + (size_t)n * ldb + c * BK + kg);
            }
        } else {
            #pragma unroll
            for (int t = 0; t < LB; t++) {
                int i = tid + t * 256;
                int r = i / (BN / 4);
                int cc = (i % (BN / 4)) * 4;
                pb[t] = *(const float4*)(B + (size_t)(c * BK + r) * ldb + cc);
            }
        }
    };
    auto storeS = [&]() {
        #pragma unroll
        for (int t = 0; t < LA; t++) {
            int i = tid + t * 256;
            int r = i >> 3;
            int cc = (i & 7) * 4;
            float4 o = make_float4(f2tf32f(pa[t].x), f2tf32f(pa[t].y),
                                   f2tf32f(pa[t].z), f2tf32f(pa[t].w));
            *(float4*)&As[r][cc] = o;
        }
        if (TRANSB) {
            #pragma unroll
            for (int t = 0; t < LB; t++) {
                int i = tid + t * 256;
                int n = i >> 3;
                int kg = (i & 7) * 4;
                Bs[kg + 0][n] = f2tf32f(pb[t].x);
                Bs[kg + 1][n] = f2tf32f(pb[t].y);
                Bs[kg + 2][n] = f2tf32f(pb[t].z);
                Bs[kg + 3][n] = f2tf32f(pb[t].w);
            }
        } else {
            #pragma unroll
            for (int t = 0; t < LB; t++) {
                int i = tid + t * 256;
                int r = i / (BN / 4);
                int cc = (i % (BN / 4)) * 4;
                float4 o = make_float4(f2tf32f(pb[t].x), f2tf32f(pb[t].y),
                                       f2tf32f(pb[t].z), f2tf32f(pb[t].w));
                *(float4*)&Bs[r][cc] = o;
            }
        }
    };

    // ---- fragment/acc setup ----
    constexpr int MS = WM / 16;
    constexpr int NS = WN / 8;
    constexpr int NWM = BM / WM;
    const int w = tid >> 5, lane = tid & 31;
    const int wm = (w % NWM) * WM;
    const int wn = (w / NWM) * WN;
    const int g = lane >> 2, tg = lane & 3;

    float acc[MS][NS][4];
    #pragma unroll
    for (int ms = 0; ms < MS; ms++)
        #pragma unroll
        for (int ns = 0; ns < NS; ns++)
            #pragma unroll
            for (int r = 0; r < 4; r++) acc[ms][ns][r] = 0.0f;

    loadA(0);
    loadB(0);

    for (int c = 0; c < NC; c++) {
        if (c) __syncthreads();
        storeS();
        __syncthreads();
        if (c + 1 < NC) { loadA(c + 1); loadB(c + 1); }

        #pragma unroll
        for (int ks = 0; ks < BK / 8; ks++) {
            float af[MS][4], bf[NS][2];
            #pragma unroll
            for (int ms = 0; ms < MS; ms++) {
                int row = wm + ms * 16 + g;
                int col = ks * 8 + tg;
                af[ms][0] = As[row][col];
                af[ms][1] = As[row + 8][col];
                af[ms][2] = As[row][col + 4];
                af[ms][3] = As[row + 8][col + 4];
            }
            #pragma unroll
            for (int ns = 0; ns < NS; ns++) {
                int bc = wn + ns * 8 + g;
                bf[ns][0] = Bs[ks * 8 + tg][bc];
                bf[ns][1] = Bs[ks * 8 + tg + 4][bc];
            }
            #pragma unroll
            for (int ms = 0; ms < MS; ms++)
                #pragma unroll
                for (int ns = 0; ns < NS; ns++)
                    mma1688(acc[ms][ns], af[ms], bf[ns]);
        }
    }

    // ---- epilogue ----
    #pragma unroll
    for (int ms = 0; ms < MS; ms++) {
        #pragma unroll
        for (int ns = 0; ns < NS; ns++) {
            int row = wm + ms * 16 + g;
            int col = wn + ns * 8 + tg * 2;
            float b0 = 0.0f, b1 = 0.0f;
            if (HASBIAS) { b0 = bias[col]; b1 = bias[col + 1]; }
            float v0 = acc[ms][ns][0] * scale + b0;
            float v1 = acc[ms][ns][1] * scale + b1;
            float v2 = acc[ms][ns][2] * scale + b0;
            float v3 = acc[ms][ns][3] * scale + b1;
            if (RELU) {
                v0 = fmaxf(v0, 0.0f); v1 = fmaxf(v1, 0.0f);
                v2 = fmaxf(v2, 0.0f); v3 = fmaxf(v3, 0.0f);
            }
            float2 o0 = make_float2(v0, v1);
            float2 o1 = make_float2(v2, v3);
            *(float2*)&C[(size_t)row * ldc + col] = o0;
            *(float2*)&C[(size_t)(row + 8) * ldc + col] = o1;
        }
    }
}

// ------------------------------- entry kernels --------------------------------------
struct QKV3 {
    const float* W[3];
    const float* b[3];
    float* o[3];
};

template <int RELU>
__global__ __launch_bounds__(256) void gemm_plain(const float* __restrict__ A,
                                                  const float* __restrict__ B,
                                                  const float* __restrict__ bias,
                                                  float* __restrict__ C, int N, int K) {
    gemm_core<128, 128, 32, 64, 32, 0, RELU, 1>(A, K, B, N, bias, C, N, K, 1.0f);
}

__global__ __launch_bounds__(256) void gemm_qkv(const float* __restrict__ A, QKV3 p) {
    int z = blockIdx.z;
    gemm_core<128, 128, 32, 64, 32, 0, 0, 1>(A, DMODEL, p.W[z], DMODEL, p.b[z],
                                              p.o[z], DMODEL, DMODEL, 1.0f);
}

__global__ __launch_bounds__(256) void gemm_scores(const float* __restrict__ q,
                                                   const float* __restrict__ k,
                                                   float* __restrict__ aw) {
    int z = blockIdx.z;
    int b = z >> 4, hh = z & 15;
    const float* A = q + (size_t)b * SEQ * DMODEL + hh * DK;
    const float* B = k + (size_t)b * SEQ * DMODEL + hh * DK;
    float* C = aw + (size_t)z * SEQ * SEQ;
    gemm_core<128, 128, 32, 64, 32, 1, 0, 0>(A, DMODEL, B, DMODEL, nullptr, C, SEQ,
                                             DK, 0.125f);
}

__global__ __launch_bounds__(256) void gemm_ctx(const float* __restrict__ aw,
                                                const float* __restrict__ v,
                                                float* __restrict__ ctx) {
    int z = blockIdx.z;
    int b = z >> 4, hh = z & 15;
    gemm_core<128, 64, 32, 32, 32, 0, 0, 0>(
        aw + (size_t)z * SEQ * SEQ, SEQ,
        v + (size_t)b * SEQ * DMODEL + hh * DK, DMODEL, nullptr,
        ctx + (size_t)b * SEQ * DMODEL + hh * DK, DMODEL, SEQ, 1.0f);
}

// ------------------------- embedding + positional encoding -------------------------
__global__ void embed_kernel(const int* __restrict__ ids, const float* __restrict__ emb,
                             float* __restrict__ h) {
    int token = blockIdx.x;
    int d = blockIdx.y * 256 + threadIdx.x;
    int s = token & (SEQ - 1);
    int id = ids[token];
    float c_even = (float)((d >> 1) << 1);
    float div = __expf(c_even * (-logf(10000.0f) / (float)DMODEL));
    float ang = (float)s * div;
    float pe = (d & 1) ? cosf(ang) : sinf(ang);
    h[(size_t)token * DMODEL + d] = emb[(size_t)id * DMODEL + d] * 32.0f + pe;
}

// ------------------------- row softmax over 1024 elements ---------------------------
__global__ void softmax1024(float* __restrict__ p0) {
    float* p = p0 + (size_t)blockIdx.x * 1024;
    const int tid = threadIdx.x;
    __shared__ float red[256];
    float vv[4];
    float m = -INFINITY;
    #pragma unroll
    for (int i = 0; i < 4; i++) { vv[i] = p[tid + i * 256]; m = fmaxf(m, vv[i]); }
    red[tid] = m; __syncthreads();
    for (int s = 128; s > 0; s >>= 1) { if (tid < s) red[tid] = fmaxf(red[tid], red[tid + s]); __syncthreads(); }
    m = red[0]; __syncthreads();
    float sum = 0.0f;
    #pragma unroll
    for (int i = 0; i < 4; i++) { vv[i] = expf(vv[i] - m); sum += vv[i]; }
    red[tid] = sum; __syncthreads();
    for (int s = 128; s > 0; s >>= 1) { if (tid < s) red[tid] += red[tid + s]; __syncthreads(); }
    float inv = 1.0f / red[0];
    #pragma unroll
    for (int i = 0; i < 4; i++) p[tid + i * 256] = vv[i] * inv;
}

// ------------------------- fused residual-add + LayerNorm ---------------------------
__global__ void add_ln_kernel(const float* __restrict__ x, const float* __restrict__ r,
                              const float* __restrict__ g, const float* __restrict__ b,
                              float* __restrict__ out) {
    const size_t row = blockIdx.x;
    const int tid = threadIdx.x;
    __shared__ float red[256];
    __shared__ float s_mu, s_rinv;
    float v[4];
    float s = 0.0f;
    #pragma unroll
    for (int i = 0; i < 4; i++) {
        int c = tid + i * 256;
        v[i] = x[row * DMODEL + c] + r[row * DMODEL + c];
        s += v[i];
    }
    red[tid] = s; __syncthreads();
    for (int t = 128; t > 0; t >>= 1) { if (tid < t) red[tid] += red[tid + t]; __syncthreads(); }
    if (tid == 0) s_mu = red[0] * (1.0f / DMODEL);
    __syncthreads();
    float mu = s_mu;
    float sq = 0.0f;
    #pragma unroll
    for (int i = 0; i < 4; i++) { float d = v[i] - mu; sq += d * d; }
    red[tid] = sq; __syncthreads();
    for (int t = 128; t > 0; t >>= 1) { if (tid < t) red[tid] += red[tid + t]; __syncthreads(); }
    if (tid == 0) s_rinv = rsqrtf(red[0] * (1.0f / DMODEL) + LNEPS);
    __syncthreads();
    float rinv = s_rinv;
    #pragma unroll
    for (int i = 0; i < 4; i++) {
        int c = tid + i * 256;
        out[row * DMODEL + c] = (v[i] - mu) * rinv * g[c] + b[c];
    }
}

// ====================================================================================
extern "C" void kernel_launch(void* const* d_in, const int* in_sizes, int n_in,
                              void* d_out, int out_size) {
    const int*   ids  = (const int*)  d_in[0];
    const float* emb  = (const float*)d_in[1];
    const float* Wq   = (const float*)d_in[2];
    const float* bq   = (const float*)d_in[3];
    const float* Wk   = (const float*)d_in[4];
    const float* bk   = (const float*)d_in[5];
    const float* Wv   = (const float*)d_in[6];
    const float* bv   = (const float*)d_in[7];
    const float* Wo   = (const float*)d_in[8];
    const float* bo   = (const float*)d_in[9];
    const float* W1   = (const float*)d_in[10];
    const float* b1   = (const float*)d_in[11];
    const float* W2   = (const float*)d_in[12];
    const float* b2   = (const float*)d_in[13];
    const float* ln1g = (const float*)d_in[14];
    const float* ln1b = (const float*)d_in[15];
    const float* ln2g = (const float*)d_in[16];
    const float* ln2b = (const float*)d_in[17];

    float* out = (float*)d_out;

    float *h, *q, *k, *v, *ctx, *res, *ff;
    cudaGetSymbolAddress((void**)&h,   g_h);
    cudaGetSymbolAddress((void**)&q,   g_q);
    cudaGetSymbolAddress((void**)&k,   g_k);
    cudaGetSymbolAddress((void**)&v,   g_v);
    cudaGetSymbolAddress((void**)&ctx, g_ctx);
    cudaGetSymbolAddress((void**)&res, g_res);
    cudaGetSymbolAddress((void**)&ff,  g_ff);

    embed_kernel<<<dim3(TOK, DMODEL / 256), 256>>>(ids, emb, h);

    dim3 gDD(DMODEL / 128, TOK / 128);       // (8, 16)
    dim3 gDF(FF / 128, TOK / 128);           // (32, 16)
    dim3 gQKV(DMODEL / 128, TOK / 128, 3);   // (8, 16, 3)
    dim3 gSC(SEQ / 128, SEQ / 128, BATCH * NHEAD);  // (8, 8, 32)
    dim3 gCX(1, SEQ / 128, BATCH * NHEAD);          // (1, 8, 32)

    for (int l = 0; l < NLAYER; l++) {
        const float* Wo_l = Wo + (size_t)l * DMODEL * DMODEL;
        const float* W1_l = W1 + (size_t)l * DMODEL * FF;
        const float* W2_l = W2 + (size_t)l * FF * DMODEL;

        float* aw = out + H_ELEMS + (size_t)l * AW_PER_LAYER;

        QKV3 p;
        p.W[0] = Wq + (size_t)l * DMODEL * DMODEL;
        p.W[1] = Wk + (size_t)l * DMODEL * DMODEL;
        p.W[2] = Wv + (size_t)l * DMODEL * DMODEL;
        p.b[0] = bq + (size_t)l * DMODEL;
        p.b[1] = bk + (size_t)l * DMODEL;
        p.b[2] = bv + (size_t)l * DMODEL;
        p.o[0] = q; p.o[1] = k; p.o[2] = v;

        gemm_qkv<<<gQKV, 256>>>(h, p);

        gemm_scores<<<gSC, 256>>>(q, k, aw);
        softmax1024<<<BATCH * NHEAD * SEQ, 256>>>(aw);
        gemm_ctx<<<gCX, 256>>>(aw, v, ctx);

        gemm_plain<0><<<gDD, 256>>>(ctx, Wo_l, bo + (size_t)l * DMODEL, res, DMODEL, DMODEL);
        add_ln_kernel<<<TOK, 256>>>(h, res, ln1g + (size_t)l * DMODEL, ln1b + (size_t)l * DMODEL, h);

        gemm_plain<1><<<gDF, 256>>>(h, W1_l, b1 + (size_t)l * FF, ff, FF, DMODEL);
        gemm_plain<0><<<gDD, 256>>>(ff, W2_l, b2 + (size_t)l * DMODEL, res, DMODEL, FF);

        float* dst = (l == NLAYER - 1) ? out : h;
        add_ln_kernel<<<TOK, 256>>>(h, res, ln2g + (size_t)l * DMODEL, ln2b + (size_t)l * DMODEL, dst);
    }
}